// round 6
// baseline (speedup 1.0000x reference)
#include <cuda_runtime.h>
#include <math_constants.h>
#include <cstdint>
#include <cstring>

#define D_DIM   256
#define CAP     16
#define MARGIN  3.5e-4f
#define MAXBT   65536
#define MAXCODE 8192

// ---------------- static device scratch (no allocations) ----------------
__device__ float         g_en[MAXCODE];
__device__ double        g_loss;
__device__ int           g_amax_bits;
__device__ unsigned char g_embs8[(size_t)MAXCODE * D_DIM];   // 2 MB int8, swizzled
__device__ float         g_cs[(size_t)MAXBT * CAP];
__device__ int           g_ci[(size_t)MAXBT * CAP];
__device__ int           g_cn[MAXBT];

// ---------------- helpers -------------------------------------------------
__device__ __forceinline__ uint32_t smem_u32(const void* p) {
    uint32_t r;
    asm("{ .reg .u64 t; cvta.to.shared.u64 t, %1; cvt.u32.u64 %0, t; }" : "=r"(r) : "l"(p));
    return r;
}
__device__ __forceinline__ void cp16(uint32_t dst, const void* src) {
    asm volatile("cp.async.cg.shared.global [%0], [%1], 16;" :: "r"(dst), "l"(src) : "memory");
}
#define CP_COMMIT() asm volatile("cp.async.commit_group;" ::: "memory")
#define CP_WAIT(n)  asm volatile("cp.async.wait_group %0;" :: "n"(n) : "memory")

__device__ __forceinline__ uint32_t pack4(int a, int b, int c, int d) {
    return (uint32_t)(a & 255) | ((uint32_t)(b & 255) << 8)
         | ((uint32_t)(c & 255) << 16) | ((uint32_t)(d & 255) << 24);
}

// ---------------- smem layout for pass1 -----------------------------------
#define A_SZ    32768
#define B_SZ    32768
#define OFF_AS  0
#define OFF_BS  A_SZ
#define OFF_CM  (OFF_BS + 2 * B_SZ)          // int[128][17]
#define OFF_RM  (OFF_CM + 128 * 17 * 4)      // int[128]
#define OFF_TH  (OFF_RM + 512)               // int[128]
#define OFF_MG  (OFF_TH + 512)               // int[128]
#define OFF_K2  (OFF_MG + 512)               // float[128]  (-2*sx*se)
#define SMEM1   (OFF_K2 + 512)               // 109056 B

// ---------------- K0: zero ------------------------------------------------
__global__ void vq_zero() {
    int i = blockIdx.x * blockDim.x + threadIdx.x;
    if (i == 0) { g_loss = 0.0; g_amax_bits = 0; }
    if (i < MAXBT) g_cn[i] = 0;
}

// ---------------- K1: global amax(|emb|) ----------------------------------
__global__ void vq_amax(const float* __restrict__ emb, int n) {
    float m = 0.f;
    for (int i = blockIdx.x * blockDim.x + threadIdx.x; i < n; i += gridDim.x * blockDim.x)
        m = fmaxf(m, fabsf(emb[i]));
#pragma unroll
    for (int o = 16; o; o >>= 1) m = fmaxf(m, __shfl_xor_sync(0xffffffffu, m, o));
    if ((threadIdx.x & 31) == 0) atomicMax(&g_amax_bits, __float_as_int(m));
}

// ---------------- K2: ||e||^2 (round-1 exact) + int8 staging --------------
__global__ void vq_stage(const float* __restrict__ emb, int ncodes) {
    int code = (blockIdx.x * blockDim.x + threadIdx.x) >> 5;
    int lane = threadIdx.x & 31;
    if (code >= ncodes) return;
    const float* e = emb + (size_t)code * D_DIM;
    float s = 0.f;
#pragma unroll
    for (int t = 0; t < 8; ++t) {
        float v = e[lane + t * 32];
        s = __fadd_rn(s, __fmul_rn(v, v));
    }
#pragma unroll
    for (int o = 16; o; o >>= 1) s = __fadd_rn(s, __shfl_xor_sync(0xffffffffu, s, o));
    if (lane == 0) g_en[code] = s;

    const float amax = fmaxf(__int_as_float(g_amax_bits), 1e-30f);
    const float inv = 127.f / amax;
    int q[8];
#pragma unroll
    for (int i = 0; i < 8; ++i) q[i] = __float2int_rn(e[lane * 8 + i] * inv);
    uint2 pk = make_uint2(pack4(q[0], q[1], q[2], q[3]), pack4(q[4], q[5], q[6], q[7]));
    int cl = code & 127;
    int g = lane >> 1;
    size_t off = (size_t)(code >> 7) * 32768 + (size_t)cl * 256
               + (uint32_t)((g ^ (cl & 15)) << 4) + (uint32_t)(lane & 1) * 8;
    *(uint2*)(g_embs8 + off) = pk;
}

// ---------------- K3: dp4a scoring + integer-threshold candidates ----------
__global__ void __launch_bounds__(256, 1)
vq_pass1(const float* __restrict__ x, int BT, int ncodes)
{
    extern __shared__ char sm[];
    const uint32_t sb = smem_u32(sm);
    const int tid = threadIdx.x, w = tid >> 5, lane = tid & 31;
    const int ty = tid >> 4, tx = tid & 15;
    const int row0 = blockIdx.x * 128;
    const int NC = ncodes >> 7;
    int*   s_cm  = (int*)(sm + OFF_CM);
    int*   s_rm  = (int*)(sm + OFF_RM);
    int*   s_thr = (int*)(sm + OFF_TH);
    int*   s_mrg = (int*)(sm + OFF_MG);
    float* s_k2  = (float*)(sm + OFF_K2);

    const float se = fmaxf(__int_as_float(g_amax_bits), 1e-30f) / 127.f;

    // per-row quantize x -> A smem (int8, XOR-swizzled 16B granules)
    for (int rr = w; rr < 128; rr += 8) {
        int gr = row0 + rr;
        float v[8];
        if (gr < BT) {
            float4 a = *(const float4*)(x + (size_t)gr * D_DIM + lane * 8);
            float4 b = *(const float4*)(x + (size_t)gr * D_DIM + lane * 8 + 4);
            v[0] = a.x; v[1] = a.y; v[2] = a.z; v[3] = a.w;
            v[4] = b.x; v[5] = b.y; v[6] = b.z; v[7] = b.w;
        } else {
#pragma unroll
            for (int i = 0; i < 8; ++i) v[i] = 0.f;
        }
        float am = 0.f;
#pragma unroll
        for (int i = 0; i < 8; ++i) am = fmaxf(am, fabsf(v[i]));
#pragma unroll
        for (int o = 16; o; o >>= 1) am = fmaxf(am, __shfl_xor_sync(0xffffffffu, am, o));
        am = fmaxf(am, 1e-30f);
        const float inv = 127.f / am;
        int q[8];
#pragma unroll
        for (int i = 0; i < 8; ++i) q[i] = __float2int_rn(v[i] * inv);
        uint2 pk = make_uint2(pack4(q[0], q[1], q[2], q[3]), pack4(q[4], q[5], q[6], q[7]));
        int g = lane >> 1;
        *(uint2*)(sm + OFF_AS + rr * 256 + (((g ^ ((rr >> 3) & 15)) << 4) | ((lane & 1) * 8))) = pk;
        if (lane == 0) {
            float sx = am / 127.f;
            s_k2[rr] = -2.f * sx * se;
            float mf = MARGIN / (2.f * sx * se);
            s_mrg[rr] = (mf > 1.0e9f) ? 0x3fffffff : ((int)mf + 1);
        }
    }
    if (tid < 128) s_rm[tid] = INT_MIN / 2;

    // prologue: chunks 0,1 -> buffers 0,1
#pragma unroll
    for (int c = 0; c < 2; ++c) {
        if (c < NC) {
            const unsigned char* src = g_embs8 + (size_t)c * 32768;
#pragma unroll
            for (int i = 0; i < 8; ++i) {
                uint32_t o = (uint32_t)(tid + i * 256) * 16u;
                cp16(sb + OFF_BS + c * B_SZ + o, src + o);
            }
        }
        CP_COMMIT();
    }

    const char* Abase = sm + OFF_AS + ty * 8 * 256;

    for (int nc = 0; nc < NC; ++nc) {
        const int buf = nc & 1;
        if (nc + 1 < NC) { CP_WAIT(1); } else { CP_WAIT(0); }
        __syncthreads();

        const char* Bbase = sm + OFF_BS + buf * B_SZ + tx * 256;
        int acc[8][8];
#pragma unroll
        for (int i = 0; i < 8; ++i)
#pragma unroll
            for (int j = 0; j < 8; ++j) acc[i][j] = 0;

#pragma unroll 1
        for (int g = 0; g < 16; ++g) {
            const uint32_t ga = (uint32_t)((g ^ ty) << 4);
            const uint32_t gb = (uint32_t)((g ^ tx) << 4);
            uint4 a4[8], b4[8];
#pragma unroll
            for (int i = 0; i < 8; ++i) a4[i] = *(const uint4*)(Abase + i * 256 + ga);
#pragma unroll
            for (int j = 0; j < 8; ++j) b4[j] = *(const uint4*)(Bbase + j * 4096 + gb);
#pragma unroll
            for (int i = 0; i < 8; ++i)
#pragma unroll
                for (int j = 0; j < 8; ++j) {
                    int t = acc[i][j];
                    t = __dp4a((int)a4[i].x, (int)b4[j].x, t);
                    t = __dp4a((int)a4[i].y, (int)b4[j].y, t);
                    t = __dp4a((int)a4[i].z, (int)b4[j].z, t);
                    t = __dp4a((int)a4[i].w, (int)b4[j].w, t);
                    acc[i][j] = t;
                }
        }

        // exact per-chunk row max (idot bigger = better) -> running threshold
#pragma unroll
        for (int i = 0; i < 8; ++i) {
            int m = acc[i][0];
#pragma unroll
            for (int j = 1; j < 8; ++j) m = max(m, acc[i][j]);
            s_cm[(ty * 8 + i) * 17 + tx] = m;
        }
        __syncthreads();

        // prefetch chunk nc+2 into freed buffer (all reads of buf done)
        if (nc + 2 < NC) {
            const unsigned char* src = g_embs8 + (size_t)(nc + 2) * 32768;
#pragma unroll
            for (int i = 0; i < 8; ++i) {
                uint32_t o = (uint32_t)(tid + i * 256) * 16u;
                cp16(sb + OFF_BS + buf * B_SZ + o, src + o);
            }
            CP_COMMIT();
        }

        if (tid < 128) {
            int m = s_cm[tid * 17];
#pragma unroll
            for (int s = 1; s < 16; ++s) m = max(m, s_cm[tid * 17 + s]);
            int rm = max(s_rm[tid], m);
            s_rm[tid] = rm;
            s_thr[tid] = rm - s_mrg[tid];
        }
        __syncthreads();

        // appends: keep codes with idot >= rowmax - margin_int
#pragma unroll
        for (int i = 0; i < 8; ++i) {
            const int rowl = ty * 8 + i;
            const int grow = row0 + rowl;
            const int th = s_thr[rowl];
            const float k2 = s_k2[rowl];
#pragma unroll
            for (int j = 0; j < 8; ++j) {
                if (acc[i][j] >= th && grow < BT) {
                    int code = nc * 128 + tx + 16 * j;
                    int pos = atomicAdd(&g_cn[grow], 1);
                    if (pos < CAP) {
                        g_cs[(size_t)grow * CAP + pos] = k2 * (float)acc[i][j];
                        g_ci[(size_t)grow * CAP + pos] = code;
                    }
                }
            }
        }
    }
}

// ---------------- K4: exact fp32 recheck (round-1 arithmetic) + epilogue --
__global__ void __launch_bounds__(256)
vq_pass2(const float* __restrict__ x, const float* __restrict__ emb,
         float* __restrict__ y_out, float* __restrict__ idx_out,
         int BT, int ncodes)
{
    __shared__ float  SX[8][256];
    __shared__ double wl[8];
    const int tid = threadIdx.x, w = tid >> 5, lane = tid & 31;
    const int r = blockIdx.x * 8 + w;
    float lsum = 0.f;

    if (r < BT) {
        {
            float4 a = *(const float4*)(x + (size_t)r * D_DIM + lane * 8);
            float4 b = *(const float4*)(x + (size_t)r * D_DIM + lane * 8 + 4);
            *(float4*)(&SX[w][lane * 8]) = a;
            *(float4*)(&SX[w][lane * 8 + 4]) = b;
        }
        __syncwarp();

        const int cntraw = g_cn[r];
        int winner;

        if (cntraw > CAP) {
            // overflow fallback: full exact scan
            float x2 = 0.f;
            for (int k = 0; k < D_DIM; ++k) {
                float xv = SX[w][k];
                x2 = __fadd_rn(x2, __fmul_rn(xv, xv));
            }
            float bd = CUDART_INF_F; int bc = 0x7fffffff;
            for (int c = lane; c < ncodes; c += 32) {
                const float* e = emb + (size_t)c * D_DIM;
                float acc = 0.f;
                for (int k = 0; k < D_DIM; ++k)
                    acc = __fmaf_rn(SX[w][k], __ldg(e + k), acc);
                float d = __fadd_rn(__fsub_rn(x2, __fmul_rn(2.0f, acc)), g_en[c]);
                if (d < bd) { bd = d; bc = c; }
            }
#pragma unroll
            for (int o = 16; o; o >>= 1) {
                float od = __shfl_xor_sync(0xffffffffu, bd, o);
                int   oc = __shfl_xor_sync(0xffffffffu, bc, o);
                if (od < bd || (od == bd && oc < bc)) { bd = od; bc = oc; }
            }
            winner = bc;
        } else {
            const int cnt = cntraw;
            float s = (lane < cnt) ? g_cs[(size_t)r * CAP + lane] : CUDART_INF_F;
            int   c = (lane < cnt) ? g_ci[(size_t)r * CAP + lane] : 0x7fffffff;
            float smin = s;
#pragma unroll
            for (int o = 16; o; o >>= 1) smin = fminf(smin, __shfl_xor_sync(0xffffffffu, smin, o));
            const bool surv = s <= smin + MARGIN;
            const int nsurv = __popc(__ballot_sync(0xffffffffu, surv));

            float d = CUDART_INF_F; int cid = 0x7fffffff;
            if (nsurv == 1) {
                if (surv) { d = 0.f; cid = c; }
            } else if (surv) {
                const float* e = emb + (size_t)c * D_DIM;
                float acc = 0.f, x2 = 0.f;
#pragma unroll 8
                for (int k = 0; k < D_DIM; ++k) {
                    float xv = SX[w][k];
                    x2  = __fadd_rn(x2, __fmul_rn(xv, xv));
                    acc = __fmaf_rn(xv, __ldg(e + k), acc);
                }
                d = __fadd_rn(__fsub_rn(x2, __fmul_rn(2.0f, acc)), g_en[c]);
                cid = c;
            }
#pragma unroll
            for (int o = 16; o; o >>= 1) {
                float od = __shfl_xor_sync(0xffffffffu, d, o);
                int   oc = __shfl_xor_sync(0xffffffffu, cid, o);
                if (od < d || (od == d && oc < cid)) { d = od; cid = oc; }
            }
            winner = cid;
        }

        if (lane == 0 && idx_out != nullptr) idx_out[r] = (float)winner;

        const float* q = emb + (size_t)winner * D_DIM;
        float4 qa = *(const float4*)(q + lane * 8);
        float4 qb = *(const float4*)(q + lane * 8 + 4);
        float qv[8], xv[8], yv[8];
        *(float4*)(qv) = qa; *(float4*)(qv + 4) = qb;
        *(float4*)(xv) = *(float4*)(&SX[w][lane * 8]);
        *(float4*)(xv + 4) = *(float4*)(&SX[w][lane * 8 + 4]);
#pragma unroll
        for (int t = 0; t < 8; ++t) {
            float df = __fsub_rn(qv[t], xv[t]);
            yv[t] = __fadd_rn(xv[t], df);
            lsum = __fmaf_rn(df, df, lsum);
        }
        *(float4*)(y_out + (size_t)r * D_DIM + lane * 8) = *(float4*)(yv);
        *(float4*)(y_out + (size_t)r * D_DIM + lane * 8 + 4) = *(float4*)(yv + 4);
    }
#pragma unroll
    for (int o = 16; o; o >>= 1) lsum += __shfl_xor_sync(0xffffffffu, lsum, o);
    if (lane == 0) wl[w] = (double)lsum;
    __syncthreads();
    if (tid == 0) {
        double t = 0.0;
#pragma unroll
        for (int i = 0; i < 8; ++i) t += wl[i];
        atomicAdd(&g_loss, t);
    }
}

__global__ void vq_fin(float* __restrict__ loss_out, double inv_n) {
    loss_out[0] = (float)(g_loss * inv_n);
}

// --------------------------------- launch ---------------------------------
extern "C" void kernel_launch(void* const* d_in, const int* in_sizes, int n_in,
                              void* d_out, int out_size)
{
    int xi = 0, ei = 1;
    if (n_in >= 2 && in_sizes[1] > in_sizes[0]) { xi = 1; ei = 0; }
    const float* x   = (const float*)d_in[xi];
    const float* emb = (const float*)d_in[ei];
    const int BT     = in_sizes[xi] / D_DIM;
    const int ncodes = in_sizes[ei] / D_DIM;

    float* out = (float*)d_out;
    const long long yN = (long long)BT * D_DIM;
    float* idxp = ((long long)out_size >= yN + BT) ? out + yN : nullptr;
    const bool has_loss = ((long long)out_size >= yN + BT + 1);

    cudaFuncSetAttribute((const void*)vq_pass1,
                         cudaFuncAttributeMaxDynamicSharedMemorySize, SMEM1);

    vq_zero<<<256, 256>>>();
    vq_amax<<<148, 256>>>(emb, ncodes * D_DIM);
    vq_stage<<<(ncodes * 32 + 255) / 256, 256>>>(emb, ncodes);
    vq_pass1<<<(BT + 127) / 128, 256, SMEM1>>>(x, BT, ncodes);
    vq_pass2<<<(BT + 7) / 8, 256>>>(x, emb, out, idxp, BT, ncodes);
    if (has_loss)
        vq_fin<<<1, 1>>>(out + yN + BT, 1.0 / ((double)BT * (double)D_DIM));
}

// round 7
// speedup vs baseline: 1.3952x; 1.3952x over previous
#include <cuda_runtime.h>
#include <math_constants.h>
#include <cstdint>

#define D_DIM     256
#define M_TILE    64
#define N_TILE    128
#define K_TILE    32
#define XS_STRIDE 68
#define ES_STRIDE 132
#define NTHREADS  256
#define MAX_CODES 16384

__device__ float  g_enorm2[MAX_CODES];
__device__ double g_loss_sum;

__global__ void vq_zero() { g_loss_sum = 0.0; }

__global__ void vq_enorm(const float* __restrict__ emb, int ncodes) {
    int warp = (blockIdx.x * blockDim.x + threadIdx.x) >> 5;
    int lane = threadIdx.x & 31;
    if (warp >= ncodes) return;
    const float* e = emb + (size_t)warp * D_DIM;
    float s = 0.f;
#pragma unroll
    for (int t = 0; t < D_DIM / 32; ++t) {
        float v = e[lane + t * 32];
        s = __fadd_rn(s, __fmul_rn(v, v));
    }
#pragma unroll
    for (int off = 16; off; off >>= 1)
        s = __fadd_rn(s, __shfl_xor_sync(0xffffffffu, s, off));
    if (lane == 0) g_enorm2[warp] = s;
}

// packed helpers ------------------------------------------------------------
__device__ __forceinline__ unsigned long long pack_dup(float a) {
    unsigned long long r; uint32_t u = __float_as_uint(a);
    asm("mov.b64 %0, {%1, %1};" : "=l"(r) : "r"(u));
    return r;
}
__device__ __forceinline__ void unpack2(unsigned long long v, float& lo, float& hi) {
    uint32_t a, b;
    asm("mov.b64 {%0, %1}, %2;" : "=r"(a), "=r"(b) : "l"(v));
    lo = __uint_as_float(a); hi = __uint_as_float(b);
}
#define FMA2(acc, a, b) \
    asm("fma.rn.f32x2 %0, %1, %2, %0;" : "+l"(acc) : "l"(a), "l"(b))

// Fused: exact fp32 GEMM (FFMA2-packed, bit-identical chains to round 1) +
// exact dist + argmin(first-index) + y/loss epilogue.
__global__ void __launch_bounds__(NTHREADS, 1)
vq_main(const float* __restrict__ x, const float* __restrict__ emb,
        float* __restrict__ y_out, float* __restrict__ idx_out,
        int BT, int ncodes)
{
    extern __shared__ float smem[];
    float*  xs = smem;
    float*  es = xs + D_DIM * XS_STRIDE;
    float*  xn = es + 2 * K_TILE * ES_STRIDE;
    float*  bd = xn + M_TILE;
    int*    bi = (int*)(bd + M_TILE * 16);
    double* warp_loss = (double*)(bi + M_TILE * 16);

    const int tid  = threadIdx.x;
    const int row0 = blockIdx.x * M_TILE;

    for (int i = tid; i < M_TILE * D_DIM; i += NTHREADS) {
        int r = i >> 8;
        int k = i & (D_DIM - 1);
        int gr = row0 + r;
        xs[k * XS_STRIDE + r] = (gr < BT) ? x[(size_t)gr * D_DIM + k] : 0.f;
    }
    __syncthreads();

    if (tid < M_TILE) {
        float s = 0.f;
#pragma unroll 8
        for (int k = 0; k < D_DIM; ++k) {
            float v = xs[k * XS_STRIDE + tid];
            s = __fadd_rn(s, __fmul_rn(v, v));
        }
        xn[tid] = s;
    }
    __syncthreads();

    const int ty = tid >> 4;
    const int tx = tid & 15;
    float axn[4];
#pragma unroll
    for (int i = 0; i < 4; ++i) axn[i] = xn[ty * 4 + i];

    float bestd[4]; int besti[4];
#pragma unroll
    for (int i = 0; i < 4; ++i) { bestd[i] = CUDART_INF_F; besti[i] = 0; }

    const int lc = tid >> 1;
    const int lp = (tid & 1) * 16;

    const int n_chunks = ncodes / N_TILE;
    for (int nc = 0; nc < n_chunks; ++nc) {
        const int n0 = nc * N_TILE;
        const float* esrc = emb + (size_t)(n0 + lc) * D_DIM + lp;

        unsigned long long acc2[4][4];
#pragma unroll
        for (int i = 0; i < 4; ++i)
#pragma unroll
            for (int j = 0; j < 4; ++j) acc2[i][j] = 0ull;

        {   // prologue k-chunk 0 -> buffer 0
            float4 st[4];
            st[0] = *(const float4*)(esrc + 0);
            st[1] = *(const float4*)(esrc + 4);
            st[2] = *(const float4*)(esrc + 8);
            st[3] = *(const float4*)(esrc + 12);
#pragma unroll
            for (int j = 0; j < 4; ++j) {
                es[(lp + j * 4 + 0) * ES_STRIDE + lc] = st[j].x;
                es[(lp + j * 4 + 1) * ES_STRIDE + lc] = st[j].y;
                es[(lp + j * 4 + 2) * ES_STRIDE + lc] = st[j].z;
                es[(lp + j * 4 + 3) * ES_STRIDE + lc] = st[j].w;
            }
        }
        __syncthreads();

#pragma unroll 1
        for (int kc = 0; kc < D_DIM / K_TILE; ++kc) {
            float4 s0, s1, s2, s3;
            const bool hn = (kc + 1 < D_DIM / K_TILE);
            if (hn) {
                const float* p = esrc + (kc + 1) * K_TILE;
                s0 = *(const float4*)(p + 0);
                s1 = *(const float4*)(p + 4);
                s2 = *(const float4*)(p + 8);
                s3 = *(const float4*)(p + 12);
            }
            const float* ec = es + (kc & 1) * (K_TILE * ES_STRIDE);
            const float* xc = xs + kc * K_TILE * XS_STRIDE;
#pragma unroll 8
            for (int kk = 0; kk < K_TILE; ++kk) {
                float4 a = *(const float4*)(xc + kk * XS_STRIDE + ty * 4);
                // b: 8 consecutive floats = 4 packed f32x2 (16B-aligned)
                ulonglong2 bb0 = *(const ulonglong2*)(ec + kk * ES_STRIDE + tx * 8);
                ulonglong2 bb1 = *(const ulonglong2*)(ec + kk * ES_STRIDE + tx * 8 + 4);
                unsigned long long b2[4] = { bb0.x, bb0.y, bb1.x, bb1.y };
                unsigned long long a2[4] = { pack_dup(a.x), pack_dup(a.y),
                                             pack_dup(a.z), pack_dup(a.w) };
#pragma unroll
                for (int i = 0; i < 4; ++i)
#pragma unroll
                    for (int j = 0; j < 4; ++j)
                        FMA2(acc2[i][j], a2[i], b2[j]);
            }
            if (hn) {
                __syncthreads();
                float* dst = es + ((kc + 1) & 1) * (K_TILE * ES_STRIDE);
                float4 st[4] = {s0, s1, s2, s3};
#pragma unroll
                for (int j = 0; j < 4; ++j) {
                    dst[(lp + j * 4 + 0) * ES_STRIDE + lc] = st[j].x;
                    dst[(lp + j * 4 + 1) * ES_STRIDE + lc] = st[j].y;
                    dst[(lp + j * 4 + 2) * ES_STRIDE + lc] = st[j].z;
                    dst[(lp + j * 4 + 3) * ES_STRIDE + lc] = st[j].w;
                }
                __syncthreads();
            }
        }

        // epilogue: unpack (bit-identical scalars) + exact dist formula
#pragma unroll
        for (int j2 = 0; j2 < 4; ++j2) {
#pragma unroll
            for (int i = 0; i < 4; ++i) {
                float dlo, dhi;
                unpack2(acc2[i][j2], dlo, dhi);
                int code0 = n0 + tx * 8 + 2 * j2;
                float en0 = g_enorm2[code0];
                float en1 = g_enorm2[code0 + 1];
                float dist0 = __fadd_rn(__fsub_rn(axn[i], __fmul_rn(2.0f, dlo)), en0);
                float dist1 = __fadd_rn(__fsub_rn(axn[i], __fmul_rn(2.0f, dhi)), en1);
                if (dist0 < bestd[i]) { bestd[i] = dist0; besti[i] = code0; }
                if (dist1 < bestd[i]) { bestd[i] = dist1; besti[i] = code0 + 1; }
            }
        }
    }

#pragma unroll
    for (int i = 0; i < 4; ++i) {
        bd[(ty * 4 + i) * 16 + tx] = bestd[i];
        bi[(ty * 4 + i) * 16 + tx] = besti[i];
    }
    __syncthreads();
    if (tid < M_TILE) {
        float d0 = bd[tid * 16]; int i0 = bi[tid * 16];
#pragma unroll
        for (int t = 1; t < 16; ++t) {
            float d = bd[tid * 16 + t]; int ii = bi[tid * 16 + t];
            if (d < d0 || (d == d0 && ii < i0)) { d0 = d; i0 = ii; }
        }
        bi[tid * 16] = i0;
        if (idx_out != nullptr && (row0 + tid) < BT)
            idx_out[row0 + tid] = (float)i0;
    }
    __syncthreads();

    float lsum = 0.f;
    for (int i = tid; i < M_TILE * D_DIM; i += NTHREADS) {
        int r = i >> 8;
        int k = i & (D_DIM - 1);
        int gr = row0 + r;
        if (gr < BT) {
            int code = bi[r * 16];
            float xv = xs[k * XS_STRIDE + r];
            float q  = __ldg(&emb[(size_t)code * D_DIM + k]);
            float df = __fsub_rn(q, xv);
            y_out[(size_t)gr * D_DIM + k] = __fadd_rn(xv, df);
            lsum = __fmaf_rn(df, df, lsum);
        }
    }
#pragma unroll
    for (int off = 16; off; off >>= 1)
        lsum += __shfl_xor_sync(0xffffffffu, lsum, off);
    if ((tid & 31) == 0) warp_loss[tid >> 5] = (double)lsum;
    __syncthreads();
    if (tid == 0) {
        double t = 0.0;
#pragma unroll
        for (int w = 0; w < NTHREADS / 32; ++w) t += warp_loss[w];
        atomicAdd(&g_loss_sum, t);
    }
}

__global__ void vq_finalize(float* __restrict__ loss_out, double inv_n) {
    loss_out[0] = (float)(g_loss_sum * inv_n);
}

extern "C" void kernel_launch(void* const* d_in, const int* in_sizes, int n_in,
                              void* d_out, int out_size)
{
    int xi = 0, ei = 1;
    if (n_in >= 2 && in_sizes[1] > in_sizes[0]) { xi = 1; ei = 0; }
    const float* x   = (const float*)d_in[xi];
    const float* emb = (const float*)d_in[ei];
    const int BT     = in_sizes[xi] / D_DIM;
    const int ncodes = in_sizes[ei] / D_DIM;

    float* out = (float*)d_out;
    const long long yN = (long long)BT * D_DIM;
    float* idxp = ((long long)out_size >= yN + BT) ? out + yN : nullptr;
    const bool has_loss = ((long long)out_size >= yN + BT + 1);

    const size_t SMEM =
        (size_t)(D_DIM * XS_STRIDE + 2 * K_TILE * ES_STRIDE + M_TILE + M_TILE * 16) * sizeof(float)
        + (size_t)(M_TILE * 16) * sizeof(int)
        + (NTHREADS / 32) * sizeof(double);
    cudaFuncSetAttribute((const void*)vq_main,
                         cudaFuncAttributeMaxDynamicSharedMemorySize, (int)SMEM);

    vq_zero<<<1, 1>>>();
    vq_enorm<<<(ncodes * 32 + 255) / 256, 256>>>(emb, ncodes);
    const int grid = (BT + M_TILE - 1) / M_TILE;
    vq_main<<<grid, NTHREADS, SMEM>>>(x, emb, out, idxp, BT, ncodes);
    if (has_loss)
        vq_finalize<<<1, 1>>>(out + yN + BT, 1.0 / ((double)BT * (double)D_DIM));
}

// round 8
// speedup vs baseline: 2.0483x; 1.4681x over previous
#include <cuda_runtime.h>
#include <cuda_fp16.h>
#include <math_constants.h>
#include <cstdint>
#include <cstring>

#define D_DIM   256
#define CAP     24
#define MARGIN  4.0e-4f            // dist units (pass2 prune)
#define MS      0.1024f            // scaled-dot margin = 512 * MARGIN / 2
#define MAXBT   65536
#define MAXCODE 8192

// ---------------- static device scratch (no allocations) ------------------
__device__ float    g_en[MAXCODE];
__device__ double   g_loss;
__device__ uint32_t g_eh2[(size_t)(MAXCODE / 128) * 16384];  // [nc][k][pair] half2, 4 MB
__device__ float    g_cs[(size_t)MAXBT * CAP];
__device__ int      g_ci[(size_t)MAXBT * CAP];
__device__ int      g_cn[MAXBT];

// ---------------- helpers ---------------------------------------------------
__device__ __forceinline__ uint32_t smem_u32(const void* p) {
    uint32_t r;
    asm("{ .reg .u64 t; cvta.to.shared.u64 t, %1; cvt.u32.u64 %0, t; }" : "=r"(r) : "l"(p));
    return r;
}
__device__ __forceinline__ void cp16(uint32_t dst, const void* src) {
    asm volatile("cp.async.cg.shared.global [%0], [%1], 16;" :: "r"(dst), "l"(src) : "memory");
}
#define CP_COMMIT() asm volatile("cp.async.commit_group;" ::: "memory")
#define CP_WAIT(n)  asm volatile("cp.async.wait_group %0;" :: "n"(n) : "memory")

__device__ __forceinline__ __half2 u2h(uint32_t u) {
    __half2 h; memcpy(&h, &u, 4); return h;
}

// ---------------- K0: zero --------------------------------------------------
__global__ void vq_zero() {
    int i = blockIdx.x * blockDim.x + threadIdx.x;
    if (i == 0) g_loss = 0.0;
    if (i < MAXBT) g_cn[i] = 0;
}

// ---------------- K1: ||e||^2, round-1 exact formula (proven) ---------------
__global__ void vq_enorm(const float* __restrict__ emb, int ncodes) {
    int code = (blockIdx.x * blockDim.x + threadIdx.x) >> 5;
    int lane = threadIdx.x & 31;
    if (code >= ncodes) return;
    const float* e = emb + (size_t)code * D_DIM;
    float s = 0.f;
#pragma unroll
    for (int t = 0; t < 8; ++t) {
        float v = e[lane + t * 32];
        s = __fadd_rn(s, __fmul_rn(v, v));
    }
#pragma unroll
    for (int o = 16; o; o >>= 1) s = __fadd_rn(s, __shfl_xor_sync(0xffffffffu, s, o));
    if (lane == 0) g_en[code] = s;
}

// ---------------- K2: stage emb as half2 code-pairs, scaled by 512 ----------
__global__ void vq_pack(const float* __restrict__ emb, int ncodes) {
    int idx = blockIdx.x * blockDim.x + threadIdx.x;
    int p = idx >> 5, lane = idx & 31;
    if (p >= ncodes / 2) return;
    int c0 = 2 * p;
    const float* e0 = emb + (size_t)c0 * D_DIM;
    const float* e1 = e0 + D_DIM;
    int nc = c0 >> 7, pl = (c0 & 127) >> 1;
    uint32_t* dst = g_eh2 + (size_t)nc * 16384 + pl;
#pragma unroll
    for (int t = 0; t < 8; ++t) {
        int k = lane * 8 + t;
        __half2 h = __floats2half2_rn(e0[k] * 512.f, e1[k] * 512.f);
        uint32_t w; memcpy(&w, &h, 4);
        dst[(size_t)k * 64] = w;
    }
}

// ---------------- K3: HFMA2 scoring + candidate collection ------------------
// smem (words): xs[256][68] dup-half2 | es[2][32][64] | s_mx[64][17] | s_run[64] | s_th[64]
#define XS_W   17408
#define ES_W   4096
#define SMEM1  ((XS_W + ES_W + 64 * 17 + 64 + 64) * 4)

__global__ void __launch_bounds__(256, 2)
vq_pass1(const float* __restrict__ x, int BT, int ncodes)
{
    extern __shared__ uint32_t sw[];
    uint32_t* xs   = sw;
    uint32_t* es   = sw + XS_W;
    float*    s_mx = (float*)(es + ES_W);
    float*    s_run = s_mx + 64 * 17;
    float*    s_th  = s_run + 64;
    const uint32_t es_b = smem_u32(es);
    const int tid = threadIdx.x, ty = tid >> 4, tx = tid & 15;
    const int row0 = blockIdx.x * 64;
    const int NC = ncodes >> 7;
    const int NSLICE = NC * 8;

    // x tile -> duplicated half2, transposed [k][row]
    for (int p = tid; p < 64 * 256; p += 256) {
        int r = p >> 8, k = p & 255, gr = row0 + r;
        float v = (gr < BT) ? x[(size_t)gr * D_DIM + k] : 0.f;
        uint32_t hb = (uint32_t)__half_as_ushort(__float2half_rn(v));
        xs[k * 68 + r] = hb | (hb << 16);
    }
    if (tid < 64) s_run[tid] = -CUDART_INF_F;

    // prologue: slices 0,1
#pragma unroll
    for (int c = 0; c < 2; ++c) {
        const uint32_t* src = g_eh2 + (size_t)c * 2048;
        cp16(es_b + (uint32_t)(c * 2048 + tid * 8) * 4, src + tid * 8);
        cp16(es_b + (uint32_t)(c * 2048 + tid * 8) * 4 + 16, src + tid * 8 + 4);
        CP_COMMIT();
    }

    __half2 acc[4][4];
#pragma unroll
    for (int i = 0; i < 4; ++i)
#pragma unroll
        for (int j = 0; j < 4; ++j) acc[i][j] = __floats2half2_rn(0.f, 0.f);

    for (int ks = 0; ks < NSLICE; ++ks) {
        const int buf = ks & 1;
        if (ks + 2 < NSLICE) { CP_WAIT(1); } else { CP_WAIT(0); }
        __syncthreads();

        const uint32_t* eb = es + buf * 2048 + tx * 4;
        const uint32_t* xb = xs + (ks & 7) * 32 * 68 + ty * 4;
#pragma unroll 8
        for (int kk = 0; kk < 32; ++kk) {
            uint4 av = *(const uint4*)(xb + kk * 68);
            uint4 bv = *(const uint4*)(eb + kk * 64);
            __half2 a0 = u2h(av.x), a1 = u2h(av.y), a2 = u2h(av.z), a3 = u2h(av.w);
            __half2 b0 = u2h(bv.x), b1 = u2h(bv.y), b2 = u2h(bv.z), b3 = u2h(bv.w);
            acc[0][0] = __hfma2(a0, b0, acc[0][0]);
            acc[0][1] = __hfma2(a0, b1, acc[0][1]);
            acc[0][2] = __hfma2(a0, b2, acc[0][2]);
            acc[0][3] = __hfma2(a0, b3, acc[0][3]);
            acc[1][0] = __hfma2(a1, b0, acc[1][0]);
            acc[1][1] = __hfma2(a1, b1, acc[1][1]);
            acc[1][2] = __hfma2(a1, b2, acc[1][2]);
            acc[1][3] = __hfma2(a1, b3, acc[1][3]);
            acc[2][0] = __hfma2(a2, b0, acc[2][0]);
            acc[2][1] = __hfma2(a2, b1, acc[2][1]);
            acc[2][2] = __hfma2(a2, b2, acc[2][2]);
            acc[2][3] = __hfma2(a2, b3, acc[2][3]);
            acc[3][0] = __hfma2(a3, b0, acc[3][0]);
            acc[3][1] = __hfma2(a3, b1, acc[3][1]);
            acc[3][2] = __hfma2(a3, b2, acc[3][2]);
            acc[3][3] = __hfma2(a3, b3, acc[3][3]);
        }
        __syncthreads();     // all reads of buf done before overwrite

        if (ks + 2 < NSLICE) {
            const uint32_t* src = g_eh2 + (size_t)(ks + 2) * 2048;
            cp16(es_b + (uint32_t)(buf * 2048 + tid * 8) * 4, src + tid * 8);
            cp16(es_b + (uint32_t)(buf * 2048 + tid * 8) * 4 + 16, src + tid * 8 + 4);
        }
        CP_COMMIT();

        if ((ks & 7) == 7) {           // chunk epilogue: 128 codes scored
            const int nc = ks >> 3;
            float sv[4][8];
#pragma unroll
            for (int i = 0; i < 4; ++i) {
                float lmax = -CUDART_INF_F;
#pragma unroll
                for (int j = 0; j < 4; ++j) {
                    float2 f = __half22float2(acc[i][j]);
                    sv[i][2 * j] = f.x; sv[i][2 * j + 1] = f.y;
                    lmax = fmaxf(lmax, fmaxf(f.x, f.y));
                    acc[i][j] = __floats2half2_rn(0.f, 0.f);
                }
                s_mx[(ty * 4 + i) * 17 + tx] = lmax;
            }
            __syncthreads();
            if (tid < 64) {
                float m = s_mx[tid * 17];
#pragma unroll
                for (int t = 1; t < 16; ++t) m = fmaxf(m, s_mx[tid * 17 + t]);
                float run = fmaxf(s_run[tid], m);
                s_run[tid] = run;
                s_th[tid] = run - MS;
            }
            __syncthreads();
#pragma unroll
            for (int i = 0; i < 4; ++i) {
                const int rowl = ty * 4 + i;
                const int grow = row0 + rowl;
                const float th = s_th[rowl];
#pragma unroll
                for (int j8 = 0; j8 < 8; ++j8) {
                    float v = sv[i][j8];
                    if (v >= th && grow < BT) {
                        int code = nc * 128 + (tx * 4 + (j8 >> 1)) * 2 + (j8 & 1);
                        int pos = atomicAdd(&g_cn[grow], 1);
                        if (pos < CAP) {
                            g_cs[(size_t)grow * CAP + pos] = -v * (1.f / 256.f);
                            g_ci[(size_t)grow * CAP + pos] = code;
                        }
                    }
                }
            }
        }
    }
}

// ---------------- K4: exact fp32 recheck (round-1 arithmetic) + epilogue ----
__global__ void __launch_bounds__(256)
vq_pass2(const float* __restrict__ x, const float* __restrict__ emb,
         float* __restrict__ y_out, float* __restrict__ idx_out,
         int BT, int ncodes)
{
    __shared__ float  SX[8][256];
    __shared__ double wl[8];
    const int tid = threadIdx.x, w = tid >> 5, lane = tid & 31;
    const int r = blockIdx.x * 8 + w;
    float lsum = 0.f;

    if (r < BT) {
        {
            float4 a = *(const float4*)(x + (size_t)r * D_DIM + lane * 8);
            float4 b = *(const float4*)(x + (size_t)r * D_DIM + lane * 8 + 4);
            *(float4*)(&SX[w][lane * 8]) = a;
            *(float4*)(&SX[w][lane * 8 + 4]) = b;
        }
        __syncwarp();

        const int cntraw = g_cn[r];
        int winner;

        if (cntraw > CAP) {
            // overflow fallback: full exact scan (round-1 arithmetic per code)
            float x2 = 0.f;
            for (int k = 0; k < D_DIM; ++k) {
                float xv = SX[w][k];
                x2 = __fadd_rn(x2, __fmul_rn(xv, xv));
            }
            float bd = CUDART_INF_F; int bc = 0x7fffffff;
            for (int c = lane; c < ncodes; c += 32) {
                const float* e = emb + (size_t)c * D_DIM;
                float acc = 0.f;
                for (int k = 0; k < D_DIM; ++k)
                    acc = __fmaf_rn(SX[w][k], __ldg(e + k), acc);
                float d = __fadd_rn(__fsub_rn(x2, __fmul_rn(2.0f, acc)), g_en[c]);
                if (d < bd) { bd = d; bc = c; }
            }
#pragma unroll
            for (int o = 16; o; o >>= 1) {
                float od = __shfl_xor_sync(0xffffffffu, bd, o);
                int   oc = __shfl_xor_sync(0xffffffffu, bc, o);
                if (od < bd || (od == bd && oc < bc)) { bd = od; bc = oc; }
            }
            winner = bc;
        } else {
            const int cnt = cntraw;
            float s = (lane < cnt) ? g_cs[(size_t)r * CAP + lane] : CUDART_INF_F;
            int   c = (lane < cnt) ? g_ci[(size_t)r * CAP + lane] : 0x7fffffff;
            float smin = s;
#pragma unroll
            for (int o = 16; o; o >>= 1) smin = fminf(smin, __shfl_xor_sync(0xffffffffu, smin, o));
            const bool surv = s <= smin + MARGIN;
            const int nsurv = __popc(__ballot_sync(0xffffffffu, surv));

            float d = CUDART_INF_F; int cid = 0x7fffffff;
            if (nsurv == 1) {
                if (surv) { d = 0.f; cid = c; }
            } else if (surv) {
                const float* e = emb + (size_t)c * D_DIM;
                float acc = 0.f, x2 = 0.f;
#pragma unroll 8
                for (int k = 0; k < D_DIM; ++k) {
                    float xv = SX[w][k];
                    x2  = __fadd_rn(x2, __fmul_rn(xv, xv));
                    acc = __fmaf_rn(xv, __ldg(e + k), acc);
                }
                d = __fadd_rn(__fsub_rn(x2, __fmul_rn(2.0f, acc)), g_en[c]);
                cid = c;
            }
#pragma unroll
            for (int o = 16; o; o >>= 1) {
                float od = __shfl_xor_sync(0xffffffffu, d, o);
                int   oc = __shfl_xor_sync(0xffffffffu, cid, o);
                if (od < d || (od == d && oc < cid)) { d = od; cid = oc; }
            }
            winner = cid;
        }

        if (lane == 0 && idx_out != nullptr) idx_out[r] = (float)winner;

        const float* q = emb + (size_t)winner * D_DIM;
        float4 qa = *(const float4*)(q + lane * 8);
        float4 qb = *(const float4*)(q + lane * 8 + 4);
        float qv[8], xv[8], yv[8];
        *(float4*)(qv) = qa; *(float4*)(qv + 4) = qb;
        *(float4*)(xv) = *(float4*)(&SX[w][lane * 8]);
        *(float4*)(xv + 4) = *(float4*)(&SX[w][lane * 8 + 4]);
#pragma unroll
        for (int t = 0; t < 8; ++t) {
            float df = __fsub_rn(qv[t], xv[t]);
            yv[t] = __fadd_rn(xv[t], df);
            lsum = __fmaf_rn(df, df, lsum);
        }
        *(float4*)(y_out + (size_t)r * D_DIM + lane * 8) = *(float4*)(yv);
        *(float4*)(y_out + (size_t)r * D_DIM + lane * 8 + 4) = *(float4*)(yv + 4);
    }
#pragma unroll
    for (int o = 16; o; o >>= 1) lsum += __shfl_xor_sync(0xffffffffu, lsum, o);
    if (lane == 0) wl[w] = (double)lsum;
    __syncthreads();
    if (tid == 0) {
        double t = 0.0;
#pragma unroll
        for (int i = 0; i < 8; ++i) t += wl[i];
        atomicAdd(&g_loss, t);
    }
}

__global__ void vq_fin(float* __restrict__ loss_out, double inv_n) {
    loss_out[0] = (float)(g_loss * inv_n);
}

// --------------------------------- launch -----------------------------------
extern "C" void kernel_launch(void* const* d_in, const int* in_sizes, int n_in,
                              void* d_out, int out_size)
{
    int xi = 0, ei = 1;
    if (n_in >= 2 && in_sizes[1] > in_sizes[0]) { xi = 1; ei = 0; }
    const float* x   = (const float*)d_in[xi];
    const float* emb = (const float*)d_in[ei];
    const int BT     = in_sizes[xi] / D_DIM;
    const int ncodes = in_sizes[ei] / D_DIM;

    float* out = (float*)d_out;
    const long long yN = (long long)BT * D_DIM;
    float* idxp = ((long long)out_size >= yN + BT) ? out + yN : nullptr;
    const bool has_loss = ((long long)out_size >= yN + BT + 1);

    cudaFuncSetAttribute((const void*)vq_pass1,
                         cudaFuncAttributeMaxDynamicSharedMemorySize, SMEM1);

    vq_zero<<<256, 256>>>();
    vq_enorm<<<(ncodes * 32 + 255) / 256, 256>>>(emb, ncodes);
    vq_pack<<<(ncodes * 16 + 255) / 256, 256>>>(emb, ncodes);
    vq_pass1<<<(BT + 63) / 64, 256, SMEM1>>>(x, BT, ncodes);
    vq_pass2<<<(BT + 7) / 8, 256>>>(x, emb, out, idxp, BT, ncodes);
    if (has_loss)
        vq_fin<<<1, 1>>>(out + yN + BT, 1.0 / ((double)BT * (double)D_DIM));
}

// round 9
// speedup vs baseline: 2.1890x; 1.0687x over previous
#include <cuda_runtime.h>
#include <cuda_fp16.h>
#include <math_constants.h>
#include <cstdint>
#include <cstring>

#define D_DIM   256
#define CAP     24
#define MARGIN  4.0e-4f            // dist units (pass2 prune)
#define MS      0.1024f            // scaled-dot margin = 512 * MARGIN / 2
#define MAXBT   65536
#define MAXCODE 8192

// ---------------- static device scratch (no allocations) ------------------
__device__ float    g_en[MAXCODE];
__device__ double   g_loss;
__device__ uint32_t g_eh2[(size_t)(MAXCODE / 256) * 32768];  // [nc2][k][pair] half2, 4 MB
__device__ float    g_cs[(size_t)MAXBT * CAP];
__device__ int      g_ci[(size_t)MAXBT * CAP];
__device__ int      g_cn[MAXBT];

// ---------------- helpers ---------------------------------------------------
__device__ __forceinline__ uint32_t smem_u32(const void* p) {
    uint32_t r;
    asm("{ .reg .u64 t; cvta.to.shared.u64 t, %1; cvt.u32.u64 %0, t; }" : "=r"(r) : "l"(p));
    return r;
}
__device__ __forceinline__ void cp16(uint32_t dst, const void* src) {
    asm volatile("cp.async.cg.shared.global [%0], [%1], 16;" :: "r"(dst), "l"(src) : "memory");
}
#define CP_COMMIT() asm volatile("cp.async.commit_group;" ::: "memory")
#define CP_WAIT(n)  asm volatile("cp.async.wait_group %0;" :: "n"(n) : "memory")

__device__ __forceinline__ __half2 u2h(uint32_t u) {
    __half2 h; memcpy(&h, &u, 4); return h;
}

// ---------------- K0: zero --------------------------------------------------
__global__ void vq_zero() {
    int i = blockIdx.x * blockDim.x + threadIdx.x;
    if (i == 0) g_loss = 0.0;
    if (i < MAXBT) g_cn[i] = 0;
}

// ---------------- K1: ||e||^2, round-1 exact formula (proven) ---------------
__global__ void vq_enorm(const float* __restrict__ emb, int ncodes) {
    int code = (blockIdx.x * blockDim.x + threadIdx.x) >> 5;
    int lane = threadIdx.x & 31;
    if (code >= ncodes) return;
    const float* e = emb + (size_t)code * D_DIM;
    float s = 0.f;
#pragma unroll
    for (int t = 0; t < 8; ++t) {
        float v = e[lane + t * 32];
        s = __fadd_rn(s, __fmul_rn(v, v));
    }
#pragma unroll
    for (int o = 16; o; o >>= 1) s = __fadd_rn(s, __shfl_xor_sync(0xffffffffu, s, o));
    if (lane == 0) g_en[code] = s;
}

// ---------------- K2: stage emb as half2 code-pairs, scaled by 512 ----------
// layout: word index = nc2*32768 + k*128 + pair   (nc2 = 256-code chunk)
__global__ void vq_pack(const float* __restrict__ emb, int ncodes) {
    int idx = blockIdx.x * blockDim.x + threadIdx.x;
    int p = idx >> 5, lane = idx & 31;
    if (p >= ncodes / 2) return;
    int c0 = 2 * p;
    const float* e0 = emb + (size_t)c0 * D_DIM;
    const float* e1 = e0 + D_DIM;
    int nc2 = c0 >> 8, pl = (c0 & 255) >> 1;
    uint32_t* dst = g_eh2 + (size_t)nc2 * 32768 + pl;
#pragma unroll
    for (int t = 0; t < 8; ++t) {
        int k = lane * 8 + t;
        __half2 h = __floats2half2_rn(e0[k] * 512.f, e1[k] * 512.f);
        uint32_t w; memcpy(&w, &h, 4);
        dst[(size_t)k * 128] = w;
    }
}

// ---------------- K3: HFMA2 scoring, 8x4 tiles, 256-code chunks -------------
// smem (words): xs[256][68] dup-half2 | es[2][32][128] | s_mx[64][33] | s_run[64] | s_th[64]
#define XS_W   17408
#define ES_W   8192
#define SMEM1  ((XS_W + ES_W + 64 * 33 + 64 + 64) * 4)

__global__ void __launch_bounds__(256, 2)
vq_pass1(const float* __restrict__ x, int BT, int ncodes)
{
    extern __shared__ uint32_t sw[];
    uint32_t* xs    = sw;                       // [k][row] dup half2
    uint32_t* es    = sw + XS_W;                // [2][32][128]
    float*    s_mx  = (float*)(es + ES_W);      // [64][33]
    float*    s_run = s_mx + 64 * 33;
    float*    s_th  = s_run + 64;
    const uint32_t es_b = smem_u32(es);
    const int tid = threadIdx.x, wid = tid >> 5, lane = tid & 31;
    const int row0 = blockIdx.x * 64;
    const int NSLICE = (ncodes >> 8) * 8;

    // x tile -> duplicated half2, transposed [k][row]
    for (int p = tid; p < 64 * 256; p += 256) {
        int r = p >> 8, k = p & 255, gr = row0 + r;
        float v = (gr < BT) ? x[(size_t)gr * D_DIM + k] : 0.f;
        uint32_t hb = (uint32_t)__half_as_ushort(__float2half_rn(v));
        xs[k * 68 + r] = hb | (hb << 16);
    }
    if (tid < 64) s_run[tid] = -CUDART_INF_F;

    // prologue: slices 0,1 (16 KB each; 4 cp16/thread)
#pragma unroll
    for (int c = 0; c < 2; ++c) {
        if (c < NSLICE) {
            const uint32_t* src = g_eh2 + (size_t)c * 4096 + tid * 16;
            uint32_t dst = es_b + (uint32_t)(c * 4096 + tid * 16) * 4;
#pragma unroll
            for (int i = 0; i < 4; ++i) cp16(dst + i * 16, src + i * 4);
        }
        CP_COMMIT();
    }

    __half2 acc[8][4];
#pragma unroll
    for (int i = 0; i < 8; ++i)
#pragma unroll
        for (int j = 0; j < 4; ++j) acc[i][j] = __floats2half2_rn(0.f, 0.f);

    for (int ks = 0; ks < NSLICE; ++ks) {
        const int buf = ks & 1;
        if (ks + 2 < NSLICE) { CP_WAIT(1); } else { CP_WAIT(0); }
        __syncthreads();

        const uint32_t* eb = es + buf * 4096 + lane * 4;
        const uint32_t* xb = xs + (ks & 7) * (32 * 68) + wid * 8;   // warp-uniform
#pragma unroll 4
        for (int kk = 0; kk < 32; ++kk) {
            uint4 av0 = *(const uint4*)(xb + kk * 68);
            uint4 av1 = *(const uint4*)(xb + kk * 68 + 4);
            uint4 bv  = *(const uint4*)(eb + kk * 128);
            __half2 a[8], b[4];
            a[0] = u2h(av0.x); a[1] = u2h(av0.y); a[2] = u2h(av0.z); a[3] = u2h(av0.w);
            a[4] = u2h(av1.x); a[5] = u2h(av1.y); a[6] = u2h(av1.z); a[7] = u2h(av1.w);
            b[0] = u2h(bv.x);  b[1] = u2h(bv.y);  b[2] = u2h(bv.z);  b[3] = u2h(bv.w);
#pragma unroll
            for (int i = 0; i < 8; ++i) {
                acc[i][0] = __hfma2(a[i], b[0], acc[i][0]);
                acc[i][1] = __hfma2(a[i], b[1], acc[i][1]);
                acc[i][2] = __hfma2(a[i], b[2], acc[i][2]);
                acc[i][3] = __hfma2(a[i], b[3], acc[i][3]);
            }
        }
        __syncthreads();     // all reads of buf done before overwrite

        if (ks + 2 < NSLICE) {
            const uint32_t* src = g_eh2 + (size_t)(ks + 2) * 4096 + tid * 16;
            uint32_t dst = es_b + (uint32_t)(buf * 4096 + tid * 16) * 4;
#pragma unroll
            for (int i = 0; i < 4; ++i) cp16(dst + i * 16, src + i * 4);
        }
        CP_COMMIT();

        if ((ks & 7) == 7) {           // chunk epilogue: 256 codes scored
            const int nc2 = ks >> 3;
            // pass A: per-row chunk max -> smem streams
#pragma unroll
            for (int i = 0; i < 8; ++i) {
                float lmax = -CUDART_INF_F;
#pragma unroll
                for (int j = 0; j < 4; ++j) {
                    float2 f = __half22float2(acc[i][j]);
                    lmax = fmaxf(lmax, fmaxf(f.x, f.y));
                }
                s_mx[(wid * 8 + i) * 33 + lane] = lmax;
            }
            __syncthreads();
            if (tid < 64) {
                float m = s_mx[tid * 33];
#pragma unroll
                for (int t = 1; t < 32; ++t) m = fmaxf(m, s_mx[tid * 33 + t]);
                float run = fmaxf(s_run[tid], m);
                s_run[tid] = run;
                s_th[tid] = run - MS;
            }
            __syncthreads();
            // pass B: appends (re-read acc), then clear acc
#pragma unroll
            for (int i = 0; i < 8; ++i) {
                const int rowl = wid * 8 + i;
                const int grow = row0 + rowl;
                const float th = s_th[rowl];
#pragma unroll
                for (int j = 0; j < 4; ++j) {
                    float2 f = __half22float2(acc[i][j]);
                    acc[i][j] = __floats2half2_rn(0.f, 0.f);
#pragma unroll
                    for (int h = 0; h < 2; ++h) {
                        float v = (h == 0) ? f.x : f.y;
                        if (v >= th && grow < BT) {
                            int code = nc2 * 256 + (lane * 4 + j) * 2 + h;
                            int pos = atomicAdd(&g_cn[grow], 1);
                            if (pos < CAP) {
                                g_cs[(size_t)grow * CAP + pos] = -v * (1.f / 256.f);
                                g_ci[(size_t)grow * CAP + pos] = code;
                            }
                        }
                    }
                }
            }
        }
    }
}

// ---------------- K4: exact fp32 recheck (round-1 arithmetic) + epilogue ----
__global__ void __launch_bounds__(256)
vq_pass2(const float* __restrict__ x, const float* __restrict__ emb,
         float* __restrict__ y_out, float* __restrict__ idx_out,
         int BT, int ncodes)
{
    __shared__ float  SX[8][256];
    __shared__ double wl[8];
    const int tid = threadIdx.x, w = tid >> 5, lane = tid & 31;
    const int r = blockIdx.x * 8 + w;
    float lsum = 0.f;

    if (r < BT) {
        {
            float4 a = *(const float4*)(x + (size_t)r * D_DIM + lane * 8);
            float4 b = *(const float4*)(x + (size_t)r * D_DIM + lane * 8 + 4);
            *(float4*)(&SX[w][lane * 8]) = a;
            *(float4*)(&SX[w][lane * 8 + 4]) = b;
        }
        __syncwarp();

        const int cntraw = g_cn[r];
        int winner;

        if (cntraw > CAP) {
            // overflow fallback: full exact scan (round-1 arithmetic per code)
            float x2 = 0.f;
            for (int k = 0; k < D_DIM; ++k) {
                float xv = SX[w][k];
                x2 = __fadd_rn(x2, __fmul_rn(xv, xv));
            }
            float bd = CUDART_INF_F; int bc = 0x7fffffff;
            for (int c = lane; c < ncodes; c += 32) {
                const float* e = emb + (size_t)c * D_DIM;
                float acc = 0.f;
                for (int k = 0; k < D_DIM; ++k)
                    acc = __fmaf_rn(SX[w][k], __ldg(e + k), acc);
                float d = __fadd_rn(__fsub_rn(x2, __fmul_rn(2.0f, acc)), g_en[c]);
                if (d < bd) { bd = d; bc = c; }
            }
#pragma unroll
            for (int o = 16; o; o >>= 1) {
                float od = __shfl_xor_sync(0xffffffffu, bd, o);
                int   oc = __shfl_xor_sync(0xffffffffu, bc, o);
                if (od < bd || (od == bd && oc < bc)) { bd = od; bc = oc; }
            }
            winner = bc;
        } else {
            const int cnt = cntraw;
            float s = (lane < cnt) ? g_cs[(size_t)r * CAP + lane] : CUDART_INF_F;
            int   c = (lane < cnt) ? g_ci[(size_t)r * CAP + lane] : 0x7fffffff;
            float smin = s;
#pragma unroll
            for (int o = 16; o; o >>= 1) smin = fminf(smin, __shfl_xor_sync(0xffffffffu, smin, o));
            const bool surv = s <= smin + MARGIN;
            const int nsurv = __popc(__ballot_sync(0xffffffffu, surv));

            float d = CUDART_INF_F; int cid = 0x7fffffff;
            if (nsurv == 1) {
                if (surv) { d = 0.f; cid = c; }
            } else if (surv) {
                const float* e = emb + (size_t)c * D_DIM;
                float acc = 0.f, x2 = 0.f;
#pragma unroll 8
                for (int k = 0; k < D_DIM; ++k) {
                    float xv = SX[w][k];
                    x2  = __fadd_rn(x2, __fmul_rn(xv, xv));
                    acc = __fmaf_rn(xv, __ldg(e + k), acc);
                }
                d = __fadd_rn(__fsub_rn(x2, __fmul_rn(2.0f, acc)), g_en[c]);
                cid = c;
            }
#pragma unroll
            for (int o = 16; o; o >>= 1) {
                float od = __shfl_xor_sync(0xffffffffu, d, o);
                int   oc = __shfl_xor_sync(0xffffffffu, cid, o);
                if (od < d || (od == d && oc < cid)) { d = od; cid = oc; }
            }
            winner = cid;
        }

        if (lane == 0 && idx_out != nullptr) idx_out[r] = (float)winner;

        const float* q = emb + (size_t)winner * D_DIM;
        float4 qa = *(const float4*)(q + lane * 8);
        float4 qb = *(const float4*)(q + lane * 8 + 4);
        float qv[8], xv[8], yv[8];
        *(float4*)(qv) = qa; *(float4*)(qv + 4) = qb;
        *(float4*)(xv) = *(float4*)(&SX[w][lane * 8]);
        *(float4*)(xv + 4) = *(float4*)(&SX[w][lane * 8 + 4]);
#pragma unroll
        for (int t = 0; t < 8; ++t) {
            float df = __fsub_rn(qv[t], xv[t]);
            yv[t] = __fadd_rn(xv[t], df);
            lsum = __fmaf_rn(df, df, lsum);
        }
        *(float4*)(y_out + (size_t)r * D_DIM + lane * 8) = *(float4*)(yv);
        *(float4*)(y_out + (size_t)r * D_DIM + lane * 8 + 4) = *(float4*)(yv + 4);
    }
#pragma unroll
    for (int o = 16; o; o >>= 1) lsum += __shfl_xor_sync(0xffffffffu, lsum, o);
    if (lane == 0) wl[w] = (double)lsum;
    __syncthreads();
    if (tid == 0) {
        double t = 0.0;
#pragma unroll
        for (int i = 0; i < 8; ++i) t += wl[i];
        atomicAdd(&g_loss, t);
    }
}

__global__ void vq_fin(float* __restrict__ loss_out, double inv_n) {
    loss_out[0] = (float)(g_loss * inv_n);
}

// --------------------------------- launch -----------------------------------
extern "C" void kernel_launch(void* const* d_in, const int* in_sizes, int n_in,
                              void* d_out, int out_size)
{
    int xi = 0, ei = 1;
    if (n_in >= 2 && in_sizes[1] > in_sizes[0]) { xi = 1; ei = 0; }
    const float* x   = (const float*)d_in[xi];
    const float* emb = (const float*)d_in[ei];
    const int BT     = in_sizes[xi] / D_DIM;
    const int ncodes = in_sizes[ei] / D_DIM;

    float* out = (float*)d_out;
    const long long yN = (long long)BT * D_DIM;
    float* idxp = ((long long)out_size >= yN + BT) ? out + yN : nullptr;
    const bool has_loss = ((long long)out_size >= yN + BT + 1);

    cudaFuncSetAttribute((const void*)vq_pass1,
                         cudaFuncAttributeMaxDynamicSharedMemorySize, SMEM1);

    vq_zero<<<256, 256>>>();
    vq_enorm<<<(ncodes * 32 + 255) / 256, 256>>>(emb, ncodes);
    vq_pack<<<(ncodes * 16 + 255) / 256, 256>>>(emb, ncodes);
    vq_pass1<<<(BT + 63) / 64, 256, SMEM1>>>(x, BT, ncodes);
    vq_pass2<<<(BT + 7) / 8, 256>>>(x, emb, out, idxp, BT, ncodes);
    if (has_loss)
        vq_fin<<<1, 1>>>(out + yN + BT, 1.0 / ((double)BT * (double)D_DIM));
}